// round 7
// baseline (speedup 1.0000x reference)
#include <cuda_runtime.h>
#include <cuda_fp16.h>
#include <cstdint>

#define BATCH 16
#define HEADS 16
#define SEQ   256
#define D     32
#define QT    32            // query rows per CTA
#define KSTR  40            // halves per K/V/Q smem row (80B pitch, LDSM conflict-free)

// halves: Ks 256*40 + Vs 256*40 + Qs 32*40 = 21760 -> 43520 B, + 1024 B stats
#define SMEM_BYTES 44544

__device__ __forceinline__ uint32_t pack_halves(__half lo, __half hi) {
    return (uint32_t)__half_as_ushort(lo) | ((uint32_t)__half_as_ushort(hi) << 16);
}

__device__ __forceinline__ uint32_t h2u(__half2 h) {
    return pack_halves(__low2half(h), __high2half(h));
}

__device__ __forceinline__ void ldsm_x4(uint32_t r[4], const __half* p) {
    uint32_t a = (uint32_t)__cvta_generic_to_shared(p);
    asm volatile("ldmatrix.sync.aligned.m8n8.x4.shared.b16 {%0,%1,%2,%3}, [%4];"
                 : "=r"(r[0]), "=r"(r[1]), "=r"(r[2]), "=r"(r[3]) : "r"(a));
}

__device__ __forceinline__ void ldsm_x4_t(uint32_t r[4], const __half* p) {
    uint32_t a = (uint32_t)__cvta_generic_to_shared(p);
    asm volatile("ldmatrix.sync.aligned.m8n8.x4.trans.shared.b16 {%0,%1,%2,%3}, [%4];"
                 : "=r"(r[0]), "=r"(r[1]), "=r"(r[2]), "=r"(r[3]) : "r"(a));
}

__device__ __forceinline__ void mma16816(float& c0, float& c1, float& c2, float& c3,
                                         uint32_t a0, uint32_t a1, uint32_t a2, uint32_t a3,
                                         uint32_t b0, uint32_t b1) {
    asm volatile(
        "mma.sync.aligned.m16n8k16.row.col.f32.f16.f16.f32 "
        "{%0,%1,%2,%3}, {%4,%5,%6,%7}, {%8,%9}, {%0,%1,%2,%3};\n"
        : "+f"(c0), "+f"(c1), "+f"(c2), "+f"(c3)
        : "r"(a0), "r"(a1), "r"(a2), "r"(a3), "r"(b0), "r"(b1));
}

__global__ __launch_bounds__(256, 3)
void attn_kernel(const float* __restrict__ gq_base,
                 const float* __restrict__ gk_base,
                 const float* __restrict__ gv_base,
                 float* __restrict__ gout_base) {
    extern __shared__ __half smem[];
    __half* Ks = smem;                    // [SEQ][KSTR]
    __half* Vs = Ks + SEQ * KSTR;         // [SEQ][KSTR]
    __half* Qs = Vs + SEQ * KSTR;         // [QT][KSTR]
    float*  stats = (float*)(Qs + QT * KSTR); // max[4][32] | sum[4][32]  (256 floats)
    float*  Ob = (float*)Ks;              // [3][32][34] partial O, aliased over dead Ks

    const int bh  = blockIdx.y;
    const int q0  = blockIdx.x * QT;
    const int tid = threadIdx.x;

    const float* gq = gq_base + (size_t)bh * SEQ * D + (size_t)q0 * D;
    const float* gk = gk_base + (size_t)bh * SEQ * D;
    const float* gv = gv_base + (size_t)bh * SEQ * D;

    // ---- Load K, V (256x32 f32) and Q (32x32 f32), convert to fp16 smem ----
    #pragma unroll
    for (int c = tid; c < SEQ * 8; c += 256) {
        int r = c >> 3, s = c & 7;
        float4 kv = ((const float4*)(gk + r * D))[s];
        float4 vv = ((const float4*)(gv + r * D))[s];
        uint2 kp = make_uint2(h2u(__floats2half2_rn(kv.x, kv.y)),
                              h2u(__floats2half2_rn(kv.z, kv.w)));
        uint2 vp = make_uint2(h2u(__floats2half2_rn(vv.x, vv.y)),
                              h2u(__floats2half2_rn(vv.z, vv.w)));
        *(uint2*)(Ks + r * KSTR + s * 4) = kp;
        *(uint2*)(Vs + r * KSTR + s * 4) = vp;
    }
    {
        int r = tid >> 3, s = tid & 7;    // QT*8 == 256 chunks exactly
        float4 qv = ((const float4*)(gq + r * D))[s];
        uint2 qp = make_uint2(h2u(__floats2half2_rn(qv.x, qv.y)),
                              h2u(__floats2half2_rn(qv.z, qv.w)));
        *(uint2*)(Qs + r * KSTR + s * 4) = qp;
    }
    __syncthreads();

    const int warp = tid >> 5;
    const int lane = tid & 31;
    const int gid  = lane >> 2;   // 0..7
    const int tig  = lane & 3;    // 0..3
    const int rt   = warp & 1;    // row tile (16 rows)
    const int kq   = warp >> 1;   // key quarter (64 cols)
    const int rowA = rt * 16;
    const int kbase = kq * 64;

    // ---- Q A-fragments via ldmatrix.x4 ----
    uint32_t aQ[2][4];
    #pragma unroll
    for (int kc = 0; kc < 2; kc++)
        ldsm_x4(aQ[kc], Qs + (rowA + (lane & 15)) * KSTR + kc * 16 + (lane >> 4) * 8);

    // ---- Phase 1: S (16x64 per warp) in registers, fp32 accum ----
    float s[8][4];
    #pragma unroll
    for (int g = 0; g < 8; g++) s[g][0] = s[g][1] = s[g][2] = s[g][3] = 0.f;

    #pragma unroll
    for (int g = 0; g < 8; g++) {
        uint32_t kb[4];
        ldsm_x4(kb, Ks + (kbase + g * 8 + (lane & 7)) * KSTR + (lane >> 3) * 8);
        mma16816(s[g][0], s[g][1], s[g][2], s[g][3],
                 aQ[0][0], aQ[0][1], aQ[0][2], aQ[0][3], kb[0], kb[1]);
        mma16816(s[g][0], s[g][1], s[g][2], s[g][3],
                 aQ[1][0], aQ[1][1], aQ[1][2], aQ[1][3], kb[2], kb[3]);
    }

    // scale + round to fp16 (packed RN, identical numerics)
    const float inv_scale = 1.0f / 5.656854249492381f;
    #pragma unroll
    for (int g = 0; g < 8; g++) {
        float2 f01 = __half22float2(__floats2half2_rn(s[g][0] * inv_scale,
                                                      s[g][1] * inv_scale));
        float2 f23 = __half22float2(__floats2half2_rn(s[g][2] * inv_scale,
                                                      s[g][3] * inv_scale));
        s[g][0] = f01.x; s[g][1] = f01.y; s[g][2] = f23.x; s[g][3] = f23.y;
    }

    // ---- Partial softmax stats over this warp's 64 keys ----
    float mlo = -1e30f, mhi = -1e30f;
    #pragma unroll
    for (int g = 0; g < 8; g++) {
        mlo = fmaxf(mlo, fmaxf(s[g][0], s[g][1]));
        mhi = fmaxf(mhi, fmaxf(s[g][2], s[g][3]));
    }
    mlo = fmaxf(mlo, __shfl_xor_sync(0xffffffffu, mlo, 1));
    mlo = fmaxf(mlo, __shfl_xor_sync(0xffffffffu, mlo, 2));
    mhi = fmaxf(mhi, __shfl_xor_sync(0xffffffffu, mhi, 1));
    mhi = fmaxf(mhi, __shfl_xor_sync(0xffffffffu, mhi, 2));

    float slo = 0.f, shi = 0.f;
    #pragma unroll
    for (int g = 0; g < 8; g++) {
        s[g][0] = __expf(s[g][0] - mlo);  slo += s[g][0];
        s[g][1] = __expf(s[g][1] - mlo);  slo += s[g][1];
        s[g][2] = __expf(s[g][2] - mhi);  shi += s[g][2];
        s[g][3] = __expf(s[g][3] - mhi);  shi += s[g][3];
    }
    slo += __shfl_xor_sync(0xffffffffu, slo, 1);
    slo += __shfl_xor_sync(0xffffffffu, slo, 2);
    shi += __shfl_xor_sync(0xffffffffu, shi, 1);
    shi += __shfl_xor_sync(0xffffffffu, shi, 2);

    if (tig == 0) {
        stats[kq * 32 + rowA + gid]           = mlo;
        stats[128 + kq * 32 + rowA + gid]     = slo;
        stats[kq * 32 + rowA + gid + 8]       = mhi;
        stats[128 + kq * 32 + rowA + gid + 8] = shi;
    }
    __syncthreads();

    // ---- 4-way combine: global max + total sum per row ----
    float scalelo, scalehi;
    {
        int r = rowA + gid;
        float m0 = stats[r],      m1 = stats[32 + r];
        float m2 = stats[64 + r], m3 = stats[96 + r];
        float gm = fmaxf(fmaxf(m0, m1), fmaxf(m2, m3));
        float tot = stats[128 + r]      * __expf(m0 - gm)
                  + stats[128 + 32 + r] * __expf(m1 - gm)
                  + stats[128 + 64 + r] * __expf(m2 - gm)
                  + stats[128 + 96 + r] * __expf(m3 - gm);
        scalelo = __expf(mlo - gm) / tot;

        int r2 = r + 8;
        float n0 = stats[r2],      n1 = stats[32 + r2];
        float n2 = stats[64 + r2], n3 = stats[96 + r2];
        float gm2 = fmaxf(fmaxf(n0, n1), fmaxf(n2, n3));
        float tot2 = stats[128 + r2]      * __expf(n0 - gm2)
                   + stats[128 + 32 + r2] * __expf(n1 - gm2)
                   + stats[128 + 64 + r2] * __expf(n2 - gm2)
                   + stats[128 + 96 + r2] * __expf(n3 - gm2);
        scalehi = __expf(mhi - gm2) / tot2;
    }

    // ---- Phase 3: O_partial = P @ V over this warp's 64 keys ----
    float o[4][4];
    #pragma unroll
    for (int nt = 0; nt < 4; nt++) o[nt][0] = o[nt][1] = o[nt][2] = o[nt][3] = 0.f;

    #pragma unroll
    for (int kc = 0; kc < 4; kc++) {
        uint32_t a0 = h2u(__floats2half2_rn(s[2*kc][0]   * scalelo, s[2*kc][1]   * scalelo));
        uint32_t a1 = h2u(__floats2half2_rn(s[2*kc][2]   * scalehi, s[2*kc][3]   * scalehi));
        uint32_t a2 = h2u(__floats2half2_rn(s[2*kc+1][0] * scalelo, s[2*kc+1][1] * scalelo));
        uint32_t a3 = h2u(__floats2half2_rn(s[2*kc+1][2] * scalehi, s[2*kc+1][3] * scalehi));

        const __half* vbase = Vs + (kbase + kc * 16 + (lane & 15)) * KSTR
                                 + ((lane >> 4) & 1) * 8;
        uint32_t vb[4];   // d cols 0-15
        ldsm_x4_t(vb, vbase);
        mma16816(o[0][0], o[0][1], o[0][2], o[0][3], a0, a1, a2, a3, vb[0], vb[1]);
        mma16816(o[1][0], o[1][1], o[1][2], o[1][3], a0, a1, a2, a3, vb[2], vb[3]);

        uint32_t vb2[4];  // d cols 16-31
        ldsm_x4_t(vb2, vbase + 16);
        mma16816(o[2][0], o[2][1], o[2][2], o[2][3], a0, a1, a2, a3, vb2[0], vb2[1]);
        mma16816(o[3][0], o[3][1], o[3][2], o[3][3], a0, a1, a2, a3, vb2[2], vb2[3]);
    }

    // ---- Combine the four key-quarters, emit ----
    if (kq != 0) {
        float* ob = Ob + (kq - 1) * (32 * 34);
        #pragma unroll
        for (int nt = 0; nt < 4; nt++) {
            int c = nt * 8 + tig * 2;
            *(float2*)&ob[(rowA + gid) * 34 + c]     = make_float2(o[nt][0], o[nt][1]);
            *(float2*)&ob[(rowA + gid + 8) * 34 + c] = make_float2(o[nt][2], o[nt][3]);
        }
    }
    __syncthreads();
    if (kq == 0) {
        float* go = gout_base + (size_t)bh * SEQ * D + (size_t)(q0 + rowA) * D;
        #pragma unroll
        for (int nt = 0; nt < 4; nt++) {
            int c = nt * 8 + tig * 2;
            float2 acc0 = make_float2(o[nt][0], o[nt][1]);
            float2 acc1 = make_float2(o[nt][2], o[nt][3]);
            #pragma unroll
            for (int p = 0; p < 3; p++) {
                const float* ob = Ob + p * (32 * 34);
                float2 plo = *(const float2*)&ob[(rowA + gid) * 34 + c];
                float2 phi = *(const float2*)&ob[(rowA + gid + 8) * 34 + c];
                acc0.x += plo.x; acc0.y += plo.y;
                acc1.x += phi.x; acc1.y += phi.y;
            }
            float2 lo = __half22float2(__floats2half2_rn(acc0.x, acc0.y));
            float2 hi = __half22float2(__floats2half2_rn(acc1.x, acc1.y));
            *(float2*)(go + (gid)     * D + c) = lo;
            *(float2*)(go + (gid + 8) * D + c) = hi;
        }
    }
}

extern "C" void kernel_launch(void* const* d_in, const int* in_sizes, int n_in,
                              void* d_out, int out_size) {
    const float* q = (const float*)d_in[0];
    const float* k = (const float*)d_in[1];
    const float* v = (const float*)d_in[2];
    float* out = (float*)d_out;

    dim3 grid(SEQ / QT, BATCH * HEADS);
    attn_kernel<<<grid, 256, SMEM_BYTES>>>(q, k, v, out);
}

// round 8
// speedup vs baseline: 1.0736x; 1.0736x over previous
#include <cuda_runtime.h>
#include <cuda_fp16.h>
#include <cstdint>

#define BATCH 16
#define HEADS 16
#define SEQ   256
#define D     32
#define QT    64            // query rows per CTA
#define KSTR  40            // halves per K/V/Q smem row (80B pitch, LDSM conflict-free)

// halves: Ks 256*40 + Vs 256*40 + Qs 64*40 = 23040 -> 46080 B, + 2048 B stats
#define SMEM_BYTES 48128

__device__ __forceinline__ uint32_t pack_halves(__half lo, __half hi) {
    return (uint32_t)__half_as_ushort(lo) | ((uint32_t)__half_as_ushort(hi) << 16);
}

__device__ __forceinline__ uint32_t h2u(__half2 h) {
    return pack_halves(__low2half(h), __high2half(h));
}

__device__ __forceinline__ void ldsm_x4(uint32_t r[4], const __half* p) {
    uint32_t a = (uint32_t)__cvta_generic_to_shared(p);
    asm volatile("ldmatrix.sync.aligned.m8n8.x4.shared.b16 {%0,%1,%2,%3}, [%4];"
                 : "=r"(r[0]), "=r"(r[1]), "=r"(r[2]), "=r"(r[3]) : "r"(a));
}

__device__ __forceinline__ void ldsm_x4_t(uint32_t r[4], const __half* p) {
    uint32_t a = (uint32_t)__cvta_generic_to_shared(p);
    asm volatile("ldmatrix.sync.aligned.m8n8.x4.trans.shared.b16 {%0,%1,%2,%3}, [%4];"
                 : "=r"(r[0]), "=r"(r[1]), "=r"(r[2]), "=r"(r[3]) : "r"(a));
}

__device__ __forceinline__ void mma16816(float* c,
                                         const uint32_t a[4],
                                         uint32_t b0, uint32_t b1) {
    asm volatile(
        "mma.sync.aligned.m16n8k16.row.col.f32.f16.f16.f32 "
        "{%0,%1,%2,%3}, {%4,%5,%6,%7}, {%8,%9}, {%0,%1,%2,%3};\n"
        : "+f"(c[0]), "+f"(c[1]), "+f"(c[2]), "+f"(c[3])
        : "r"(a[0]), "r"(a[1]), "r"(a[2]), "r"(a[3]), "r"(b0), "r"(b1));
}

__global__ __launch_bounds__(256, 2)
void attn_kernel(const float* __restrict__ gq_base,
                 const float* __restrict__ gk_base,
                 const float* __restrict__ gv_base,
                 float* __restrict__ gout_base) {
    extern __shared__ __half smem[];
    __half* Ks = smem;                    // [SEQ][KSTR]
    __half* Vs = Ks + SEQ * KSTR;         // [SEQ][KSTR]
    __half* Qs = Vs + SEQ * KSTR;         // [QT][KSTR]
    float*  stats = (float*)(Qs + QT * KSTR); // max[4][64] | sum[4][64]  (512 floats)
    float*  Ob = (float*)Ks;              // 2 slots of [64][34], aliased over dead Ks

    const int bh  = blockIdx.y;
    const int q0  = blockIdx.x * QT;
    const int tid = threadIdx.x;

    const float* gq = gq_base + (size_t)bh * SEQ * D + (size_t)q0 * D;
    const float* gk = gk_base + (size_t)bh * SEQ * D;
    const float* gv = gv_base + (size_t)bh * SEQ * D;

    // ---- Load K, V (256x32 f32) and Q (64x32 f32), convert to fp16 smem ----
    #pragma unroll
    for (int c = tid; c < SEQ * 8; c += 256) {
        int r = c >> 3, s = c & 7;
        float4 kv = ((const float4*)(gk + r * D))[s];
        float4 vv = ((const float4*)(gv + r * D))[s];
        uint2 kp = make_uint2(h2u(__floats2half2_rn(kv.x, kv.y)),
                              h2u(__floats2half2_rn(kv.z, kv.w)));
        uint2 vp = make_uint2(h2u(__floats2half2_rn(vv.x, vv.y)),
                              h2u(__floats2half2_rn(vv.z, vv.w)));
        *(uint2*)(Ks + r * KSTR + s * 4) = kp;
        *(uint2*)(Vs + r * KSTR + s * 4) = vp;
    }
    #pragma unroll
    for (int c = tid; c < QT * 8; c += 256) {
        int r = c >> 3, s = c & 7;
        float4 qv = ((const float4*)(gq + r * D))[s];
        uint2 qp = make_uint2(h2u(__floats2half2_rn(qv.x, qv.y)),
                              h2u(__floats2half2_rn(qv.z, qv.w)));
        *(uint2*)(Qs + r * KSTR + s * 4) = qp;
    }
    __syncthreads();

    const int warp = tid >> 5;
    const int lane = tid & 31;
    const int gid  = lane >> 2;   // 0..7
    const int tig  = lane & 3;    // 0..3
    const int rg   = warp & 1;    // row group (32 rows)
    const int kq   = warp >> 1;   // key quarter (64 cols)
    const int rowA = rg * 32;
    const int kbase = kq * 64;

    // ---- Q A-fragments: 2 row-tiles x 2 k-chunks ----
    uint32_t aQ[2][2][4];
    #pragma unroll
    for (int rt = 0; rt < 2; rt++)
        #pragma unroll
        for (int kc = 0; kc < 2; kc++)
            ldsm_x4(aQ[rt][kc],
                    Qs + (rowA + rt * 16 + (lane & 15)) * KSTR + kc * 16 + (lane >> 4) * 8);

    // ---- Phase 1: S (32 rows x 64 keys per warp), fp32 accum ----
    float s[2][8][4];
    #pragma unroll
    for (int rt = 0; rt < 2; rt++)
        #pragma unroll
        for (int g = 0; g < 8; g++)
            s[rt][g][0] = s[rt][g][1] = s[rt][g][2] = s[rt][g][3] = 0.f;

    #pragma unroll
    for (int g = 0; g < 8; g++) {
        uint32_t kb[4];   // 8 keys x 32 dims
        ldsm_x4(kb, Ks + (kbase + g * 8 + (lane & 7)) * KSTR + (lane >> 3) * 8);
        #pragma unroll
        for (int rt = 0; rt < 2; rt++) {
            mma16816(s[rt][g], aQ[rt][0], kb[0], kb[1]);
            mma16816(s[rt][g], aQ[rt][1], kb[2], kb[3]);
        }
    }

    // scale + round to fp16 (packed RN, identical numerics)
    const float inv_scale = 1.0f / 5.656854249492381f;
    #pragma unroll
    for (int rt = 0; rt < 2; rt++)
        #pragma unroll
        for (int g = 0; g < 8; g++) {
            float2 f01 = __half22float2(__floats2half2_rn(s[rt][g][0] * inv_scale,
                                                          s[rt][g][1] * inv_scale));
            float2 f23 = __half22float2(__floats2half2_rn(s[rt][g][2] * inv_scale,
                                                          s[rt][g][3] * inv_scale));
            s[rt][g][0] = f01.x; s[rt][g][1] = f01.y;
            s[rt][g][2] = f23.x; s[rt][g][3] = f23.y;
        }

    // ---- Partial softmax stats over this warp's 64 keys (4 row positions) ----
    float pm[2][2], ps[2][2];
    #pragma unroll
    for (int rt = 0; rt < 2; rt++) {
        float mlo = -1e30f, mhi = -1e30f;
        #pragma unroll
        for (int g = 0; g < 8; g++) {
            mlo = fmaxf(mlo, fmaxf(s[rt][g][0], s[rt][g][1]));
            mhi = fmaxf(mhi, fmaxf(s[rt][g][2], s[rt][g][3]));
        }
        mlo = fmaxf(mlo, __shfl_xor_sync(0xffffffffu, mlo, 1));
        mlo = fmaxf(mlo, __shfl_xor_sync(0xffffffffu, mlo, 2));
        mhi = fmaxf(mhi, __shfl_xor_sync(0xffffffffu, mhi, 1));
        mhi = fmaxf(mhi, __shfl_xor_sync(0xffffffffu, mhi, 2));

        float slo = 0.f, shi = 0.f;
        #pragma unroll
        for (int g = 0; g < 8; g++) {
            s[rt][g][0] = __expf(s[rt][g][0] - mlo);  slo += s[rt][g][0];
            s[rt][g][1] = __expf(s[rt][g][1] - mlo);  slo += s[rt][g][1];
            s[rt][g][2] = __expf(s[rt][g][2] - mhi);  shi += s[rt][g][2];
            s[rt][g][3] = __expf(s[rt][g][3] - mhi);  shi += s[rt][g][3];
        }
        slo += __shfl_xor_sync(0xffffffffu, slo, 1);
        slo += __shfl_xor_sync(0xffffffffu, slo, 2);
        shi += __shfl_xor_sync(0xffffffffu, shi, 1);
        shi += __shfl_xor_sync(0xffffffffu, shi, 2);

        pm[rt][0] = mlo; pm[rt][1] = mhi;
        ps[rt][0] = slo; ps[rt][1] = shi;
        if (tig == 0) {
            int r = rowA + rt * 16 + gid;
            stats[kq * 64 + r]           = mlo;
            stats[256 + kq * 64 + r]     = slo;
            stats[kq * 64 + r + 8]       = mhi;
            stats[256 + kq * 64 + r + 8] = shi;
        }
    }
    __syncthreads();

    // ---- 4-way combine -> per-row probability scale for this warp's partial ----
    float pscale[2][2];
    #pragma unroll
    for (int rt = 0; rt < 2; rt++)
        #pragma unroll
        for (int hf = 0; hf < 2; hf++) {
            int r = rowA + rt * 16 + gid + hf * 8;
            float m0 = stats[r],       m1 = stats[64 + r];
            float m2 = stats[128 + r], m3 = stats[192 + r];
            float gm = fmaxf(fmaxf(m0, m1), fmaxf(m2, m3));
            float tot = stats[256 + r]       * __expf(m0 - gm)
                      + stats[256 + 64 + r]  * __expf(m1 - gm)
                      + stats[256 + 128 + r] * __expf(m2 - gm)
                      + stats[256 + 192 + r] * __expf(m3 - gm);
            pscale[rt][hf] = __expf(pm[rt][hf] - gm) / tot;
        }

    // ---- Phase 3: O_partial = P @ V over this warp's 64 keys ----
    float o[2][4][4];
    #pragma unroll
    for (int rt = 0; rt < 2; rt++)
        #pragma unroll
        for (int nt = 0; nt < 4; nt++)
            o[rt][nt][0] = o[rt][nt][1] = o[rt][nt][2] = o[rt][nt][3] = 0.f;

    #pragma unroll
    for (int kc = 0; kc < 4; kc++) {
        const __half* vbase = Vs + (kbase + kc * 16 + (lane & 15)) * KSTR
                                 + ((lane >> 4) & 1) * 8;
        uint32_t vb[4];   // d cols 0-15
        ldsm_x4_t(vb, vbase);
        uint32_t vb2[4];  // d cols 16-31
        ldsm_x4_t(vb2, vbase + 16);

        #pragma unroll
        for (int rt = 0; rt < 2; rt++) {
            uint32_t a[4];
            a[0] = h2u(__floats2half2_rn(s[rt][2*kc][0]   * pscale[rt][0],
                                         s[rt][2*kc][1]   * pscale[rt][0]));
            a[1] = h2u(__floats2half2_rn(s[rt][2*kc][2]   * pscale[rt][1],
                                         s[rt][2*kc][3]   * pscale[rt][1]));
            a[2] = h2u(__floats2half2_rn(s[rt][2*kc+1][0] * pscale[rt][0],
                                         s[rt][2*kc+1][1] * pscale[rt][0]));
            a[3] = h2u(__floats2half2_rn(s[rt][2*kc+1][2] * pscale[rt][1],
                                         s[rt][2*kc+1][3] * pscale[rt][1]));
            mma16816(o[rt][0], a, vb[0], vb[1]);
            mma16816(o[rt][1], a, vb[2], vb[3]);
            mma16816(o[rt][2], a, vb2[0], vb2[1]);
            mma16816(o[rt][3], a, vb2[2], vb2[3]);
        }
    }

    // ---- Deterministic 4-way O reduction over 2 smem slots ----
    // Stage A: kq 1 -> slot 0, kq 3 -> slot 1
    if (kq & 1) {
        float* ob = Ob + (kq >> 1) * (64 * 34);
        #pragma unroll
        for (int rt = 0; rt < 2; rt++)
            #pragma unroll
            for (int nt = 0; nt < 4; nt++) {
                int r = rowA + rt * 16 + gid, c = nt * 8 + tig * 2;
                *(float2*)&ob[r * 34 + c]       = make_float2(o[rt][nt][0], o[rt][nt][1]);
                *(float2*)&ob[(r + 8) * 34 + c] = make_float2(o[rt][nt][2], o[rt][nt][3]);
            }
    }
    __syncthreads();

    // Stage B: kq 0 adds slot 0, kq 2 adds slot 1; kq 2 re-writes slot 1
    if (!(kq & 1)) {
        const float* ob = Ob + (kq >> 1) * (64 * 34);
        #pragma unroll
        for (int rt = 0; rt < 2; rt++)
            #pragma unroll
            for (int nt = 0; nt < 4; nt++) {
                int r = rowA + rt * 16 + gid, c = nt * 8 + tig * 2;
                float2 plo = *(const float2*)&ob[r * 34 + c];
                float2 phi = *(const float2*)&ob[(r + 8) * 34 + c];
                o[rt][nt][0] += plo.x; o[rt][nt][1] += plo.y;
                o[rt][nt][2] += phi.x; o[rt][nt][3] += phi.y;
            }
    }
    __syncthreads();
    if (kq == 2) {
        float* ob = Ob + (64 * 34);
        #pragma unroll
        for (int rt = 0; rt < 2; rt++)
            #pragma unroll
            for (int nt = 0; nt < 4; nt++) {
                int r = rowA + rt * 16 + gid, c = nt * 8 + tig * 2;
                *(float2*)&ob[r * 34 + c]       = make_float2(o[rt][nt][0], o[rt][nt][1]);
                *(float2*)&ob[(r + 8) * 34 + c] = make_float2(o[rt][nt][2], o[rt][nt][3]);
            }
    }
    __syncthreads();

    // Stage C: kq 0 adds combined (2+3), rounds to fp16, widens, emits
    if (kq == 0) {
        const float* ob = Ob + (64 * 34);
        float* go = gout_base + (size_t)bh * SEQ * D + (size_t)q0 * D;
        #pragma unroll
        for (int rt = 0; rt < 2; rt++)
            #pragma unroll
            for (int nt = 0; nt < 4; nt++) {
                int r = rowA + rt * 16 + gid, c = nt * 8 + tig * 2;
                float2 plo = *(const float2*)&ob[r * 34 + c];
                float2 phi = *(const float2*)&ob[(r + 8) * 34 + c];
                float2 lo = __half22float2(__floats2half2_rn(o[rt][nt][0] + plo.x,
                                                             o[rt][nt][1] + plo.y));
                float2 hi = __half22float2(__floats2half2_rn(o[rt][nt][2] + phi.x,
                                                             o[rt][nt][3] + phi.y));
                *(float2*)(go + r * D + c)       = lo;
                *(float2*)(go + (r + 8) * D + c) = hi;
            }
    }
}

extern "C" void kernel_launch(void* const* d_in, const int* in_sizes, int n_in,
                              void* d_out, int out_size) {
    const float* q = (const float*)d_in[0];
    const float* k = (const float*)d_in[1];
    const float* v = (const float*)d_in[2];
    float* out = (float*)d_out;

    dim3 grid(SEQ / QT, BATCH * HEADS);
    attn_kernel<<<grid, 256, SMEM_BYTES>>>(q, k, v, out);
}

// round 9
// speedup vs baseline: 1.2782x; 1.1905x over previous
#include <cuda_runtime.h>
#include <cuda_fp16.h>
#include <cstdint>

#define BATCH 16
#define HEADS 16
#define SEQ   256
#define D     32
#define QT    64            // query rows per CTA
#define KSTR  40            // halves per K/V/Q smem row (80B pitch, LDSM conflict-free)

// halves: Ks 256*40 + Vs 256*40 + Qs 64*40 = 23040 -> 46080 B, + 1024 B stats
#define SMEM_BYTES 47104

__device__ __forceinline__ uint32_t pack_halves(__half lo, __half hi) {
    return (uint32_t)__half_as_ushort(lo) | ((uint32_t)__half_as_ushort(hi) << 16);
}

__device__ __forceinline__ uint32_t h2u(__half2 h) {
    return pack_halves(__low2half(h), __high2half(h));
}

__device__ __forceinline__ void ldsm_x4(uint32_t r[4], const __half* p) {
    uint32_t a = (uint32_t)__cvta_generic_to_shared(p);
    asm volatile("ldmatrix.sync.aligned.m8n8.x4.shared.b16 {%0,%1,%2,%3}, [%4];"
                 : "=r"(r[0]), "=r"(r[1]), "=r"(r[2]), "=r"(r[3]) : "r"(a));
}

__device__ __forceinline__ void ldsm_x4_t(uint32_t r[4], const __half* p) {
    uint32_t a = (uint32_t)__cvta_generic_to_shared(p);
    asm volatile("ldmatrix.sync.aligned.m8n8.x4.trans.shared.b16 {%0,%1,%2,%3}, [%4];"
                 : "=r"(r[0]), "=r"(r[1]), "=r"(r[2]), "=r"(r[3]) : "r"(a));
}

__device__ __forceinline__ void mma16816(float* c, const uint32_t a[4],
                                         uint32_t b0, uint32_t b1) {
    asm volatile(
        "mma.sync.aligned.m16n8k16.row.col.f32.f16.f16.f32 "
        "{%0,%1,%2,%3}, {%4,%5,%6,%7}, {%8,%9}, {%0,%1,%2,%3};\n"
        : "+f"(c[0]), "+f"(c[1]), "+f"(c[2]), "+f"(c[3])
        : "r"(a[0]), "r"(a[1]), "r"(a[2]), "r"(a[3]), "r"(b0), "r"(b1));
}

__global__ __launch_bounds__(256, 3)
void attn_kernel(const float* __restrict__ gq_base,
                 const float* __restrict__ gk_base,
                 const float* __restrict__ gv_base,
                 float* __restrict__ gout_base) {
    extern __shared__ __half smem[];
    __half* Ks = smem;                    // [SEQ][KSTR]
    __half* Vs = Ks + SEQ * KSTR;         // [SEQ][KSTR]
    __half* Qs = Vs + SEQ * KSTR;         // [QT][KSTR]
    float*  stats = (float*)(Qs + QT * KSTR); // max[2][64] | sum[2][64]  (256 floats)
    float*  Ob = (float*)Ks;              // [64][34] partial O, aliased over dead Ks

    const int bh  = blockIdx.y;
    const int q0  = blockIdx.x * QT;
    const int tid = threadIdx.x;

    const float* gq = gq_base + (size_t)bh * SEQ * D + (size_t)q0 * D;
    const float* gk = gk_base + (size_t)bh * SEQ * D;
    const float* gv = gv_base + (size_t)bh * SEQ * D;

    // ---- Load K, V (256x32 f32) and Q (64x32 f32), convert to fp16 smem ----
    #pragma unroll
    for (int c = tid; c < SEQ * 8; c += 256) {
        int r = c >> 3, s = c & 7;
        float4 kv = ((const float4*)(gk + r * D))[s];
        float4 vv = ((const float4*)(gv + r * D))[s];
        uint2 kp = make_uint2(h2u(__floats2half2_rn(kv.x, kv.y)),
                              h2u(__floats2half2_rn(kv.z, kv.w)));
        uint2 vp = make_uint2(h2u(__floats2half2_rn(vv.x, vv.y)),
                              h2u(__floats2half2_rn(vv.z, vv.w)));
        *(uint2*)(Ks + r * KSTR + s * 4) = kp;
        *(uint2*)(Vs + r * KSTR + s * 4) = vp;
    }
    #pragma unroll
    for (int c = tid; c < QT * 8; c += 256) {
        int r = c >> 3, s = c & 7;
        float4 qv = ((const float4*)(gq + r * D))[s];
        uint2 qp = make_uint2(h2u(__floats2half2_rn(qv.x, qv.y)),
                              h2u(__floats2half2_rn(qv.z, qv.w)));
        *(uint2*)(Qs + r * KSTR + s * 4) = qp;
    }
    __syncthreads();

    const int warp = tid >> 5;
    const int lane = tid & 31;
    const int gid  = lane >> 2;   // 0..7
    const int tig  = lane & 3;    // 0..3
    const int rt   = warp & 3;    // row tile (16 rows)
    const int kh   = warp >> 2;   // key half (128 cols)
    const int rowA = rt * 16;

    // ---- Q A-fragments via ldmatrix.x4 ----
    uint32_t aQ[2][4];
    #pragma unroll
    for (int kc = 0; kc < 2; kc++)
        ldsm_x4(aQ[kc], Qs + (rowA + (lane & 15)) * KSTR + kc * 16 + (lane >> 4) * 8);

    const float inv_scale = 1.0f / 5.656854249492381f;

    // ---- Online two-chunk processing of this warp's 128 keys ----
    float o[4][4];
    #pragma unroll
    for (int nt = 0; nt < 4; nt++) o[nt][0] = o[nt][1] = o[nt][2] = o[nt][3] = 0.f;
    float m_lo = -1e30f, m_hi = -1e30f, sum_lo = 0.f, sum_hi = 0.f;

    #pragma unroll
    for (int ch = 0; ch < 2; ch++) {
        const int cb = kh * 128 + ch * 64;

        // QK^T for 16 rows x 64 keys (fp32 accum)
        float s[8][4];
        #pragma unroll
        for (int g = 0; g < 8; g++) s[g][0] = s[g][1] = s[g][2] = s[g][3] = 0.f;
        #pragma unroll
        for (int g = 0; g < 8; g++) {
            uint32_t kb[4];
            ldsm_x4(kb, Ks + (cb + g * 8 + (lane & 7)) * KSTR + (lane >> 3) * 8);
            mma16816(s[g], aQ[0], kb[0], kb[1]);
            mma16816(s[g], aQ[1], kb[2], kb[3]);
        }

        // scale + round to fp16 (packed RN, same as all passing rounds)
        #pragma unroll
        for (int g = 0; g < 8; g++) {
            float2 f01 = __half22float2(__floats2half2_rn(s[g][0] * inv_scale,
                                                          s[g][1] * inv_scale));
            float2 f23 = __half22float2(__floats2half2_rn(s[g][2] * inv_scale,
                                                          s[g][3] * inv_scale));
            s[g][0] = f01.x; s[g][1] = f01.y; s[g][2] = f23.x; s[g][3] = f23.y;
        }

        // chunk max (per row half), reduced across the quad
        float cm_lo = -1e30f, cm_hi = -1e30f;
        #pragma unroll
        for (int g = 0; g < 8; g++) {
            cm_lo = fmaxf(cm_lo, fmaxf(s[g][0], s[g][1]));
            cm_hi = fmaxf(cm_hi, fmaxf(s[g][2], s[g][3]));
        }
        cm_lo = fmaxf(cm_lo, __shfl_xor_sync(0xffffffffu, cm_lo, 1));
        cm_lo = fmaxf(cm_lo, __shfl_xor_sync(0xffffffffu, cm_lo, 2));
        cm_hi = fmaxf(cm_hi, __shfl_xor_sync(0xffffffffu, cm_hi, 1));
        cm_hi = fmaxf(cm_hi, __shfl_xor_sync(0xffffffffu, cm_hi, 2));

        // online merge: rescale running O and sum
        float nm_lo = fmaxf(m_lo, cm_lo), nm_hi = fmaxf(m_hi, cm_hi);
        float al_lo = __expf(m_lo - nm_lo), al_hi = __expf(m_hi - nm_hi);
        #pragma unroll
        for (int nt = 0; nt < 4; nt++) {
            o[nt][0] *= al_lo; o[nt][1] *= al_lo;
            o[nt][2] *= al_hi; o[nt][3] *= al_hi;
        }

        float cs_lo = 0.f, cs_hi = 0.f;
        #pragma unroll
        for (int g = 0; g < 8; g++) {
            s[g][0] = __expf(s[g][0] - nm_lo);  cs_lo += s[g][0];
            s[g][1] = __expf(s[g][1] - nm_lo);  cs_lo += s[g][1];
            s[g][2] = __expf(s[g][2] - nm_hi);  cs_hi += s[g][2];
            s[g][3] = __expf(s[g][3] - nm_hi);  cs_hi += s[g][3];
        }
        cs_lo += __shfl_xor_sync(0xffffffffu, cs_lo, 1);
        cs_lo += __shfl_xor_sync(0xffffffffu, cs_lo, 2);
        cs_hi += __shfl_xor_sync(0xffffffffu, cs_hi, 1);
        cs_hi += __shfl_xor_sync(0xffffffffu, cs_hi, 2);

        sum_lo = sum_lo * al_lo + cs_lo;
        sum_hi = sum_hi * al_hi + cs_hi;
        m_lo = nm_lo; m_hi = nm_hi;

        // PV over this chunk: P = fp16(exp(s - m)), normalization deferred to O
        #pragma unroll
        for (int kc = 0; kc < 4; kc++) {
            uint32_t a[4];
            a[0] = h2u(__floats2half2_rn(s[2*kc][0],   s[2*kc][1]));
            a[1] = h2u(__floats2half2_rn(s[2*kc][2],   s[2*kc][3]));
            a[2] = h2u(__floats2half2_rn(s[2*kc+1][0], s[2*kc+1][1]));
            a[3] = h2u(__floats2half2_rn(s[2*kc+1][2], s[2*kc+1][3]));

            const __half* vbase = Vs + (cb + kc * 16 + (lane & 15)) * KSTR
                                     + ((lane >> 4) & 1) * 8;
            uint32_t vb[4];   // d cols 0-15
            ldsm_x4_t(vb, vbase);
            mma16816(o[0], a, vb[0], vb[1]);
            mma16816(o[1], a, vb[2], vb[3]);
            uint32_t vb2[4];  // d cols 16-31
            ldsm_x4_t(vb2, vbase + 16);
            mma16816(o[2], a, vb2[0], vb2[1]);
            mma16816(o[3], a, vb2[2], vb2[3]);
        }
    }

    // ---- Cross-warp (2-way) softmax combine ----
    if (tig == 0) {
        stats[kh * 64 + rowA + gid]           = m_lo;
        stats[128 + kh * 64 + rowA + gid]     = sum_lo;
        stats[kh * 64 + rowA + gid + 8]       = m_hi;
        stats[128 + kh * 64 + rowA + gid + 8] = sum_hi;
    }
    __syncthreads();

    float sc_lo, sc_hi;
    {
        int r = rowA + gid;
        float m0 = stats[r], m1 = stats[64 + r];
        float gm = fmaxf(m0, m1);
        float tot = stats[128 + r] * __expf(m0 - gm) + stats[192 + r] * __expf(m1 - gm);
        sc_lo = __expf(m_lo - gm) / tot;

        int r2 = r + 8;
        float n0 = stats[r2], n1 = stats[64 + r2];
        float gm2 = fmaxf(n0, n1);
        float tot2 = stats[128 + r2] * __expf(n0 - gm2) + stats[192 + r2] * __expf(n1 - gm2);
        sc_hi = __expf(m_hi - gm2) / tot2;
    }
    #pragma unroll
    for (int nt = 0; nt < 4; nt++) {
        o[nt][0] *= sc_lo; o[nt][1] *= sc_lo;
        o[nt][2] *= sc_hi; o[nt][3] *= sc_hi;
    }

    // ---- Combine the two key-halves, emit ----
    if (kh == 1) {
        #pragma unroll
        for (int nt = 0; nt < 4; nt++) {
            int c = nt * 8 + tig * 2;
            *(float2*)&Ob[(rowA + gid) * 34 + c]     = make_float2(o[nt][0], o[nt][1]);
            *(float2*)&Ob[(rowA + gid + 8) * 34 + c] = make_float2(o[nt][2], o[nt][3]);
        }
    }
    __syncthreads();
    if (kh == 0) {
        float* go = gout_base + (size_t)bh * SEQ * D + (size_t)(q0 + rowA) * D;
        #pragma unroll
        for (int nt = 0; nt < 4; nt++) {
            int c = nt * 8 + tig * 2;
            float2 plo = *(const float2*)&Ob[(rowA + gid) * 34 + c];
            float2 phi = *(const float2*)&Ob[(rowA + gid + 8) * 34 + c];
            float2 lo = __half22float2(__floats2half2_rn(o[nt][0] + plo.x, o[nt][1] + plo.y));
            float2 hi = __half22float2(__floats2half2_rn(o[nt][2] + phi.x, o[nt][3] + phi.y));
            *(float2*)(go + (gid)     * D + c) = lo;
            *(float2*)(go + (gid + 8) * D + c) = hi;
        }
    }
}

extern "C" void kernel_launch(void* const* d_in, const int* in_sizes, int n_in,
                              void* d_out, int out_size) {
    const float* q = (const float*)d_in[0];
    const float* k = (const float*)d_in[1];
    const float* v = (const float*)d_in[2];
    float* out = (float*)d_out;

    dim3 grid(SEQ / QT, BATCH * HEADS);
    attn_kernel<<<grid, 256, SMEM_BYTES>>>(q, k, v, out);
}

// round 10
// speedup vs baseline: 1.3840x; 1.0828x over previous
#include <cuda_runtime.h>
#include <cuda_fp16.h>
#include <cstdint>

#define BATCH 16
#define HEADS 16
#define SEQ   256
#define D     32
#define QT    128           // query rows per CTA (one warp = 16 rows x all 256 keys)
#define KSTR  40            // halves per K/V/Q smem row (80B pitch, LDSM conflict-free)

// halves: Ks 256*40 + Vs 256*40 + Qs 128*40 = 25600 -> 51200 B
#define SMEM_BYTES 51200

__device__ __forceinline__ uint32_t pack_halves(__half lo, __half hi) {
    return (uint32_t)__half_as_ushort(lo) | ((uint32_t)__half_as_ushort(hi) << 16);
}

__device__ __forceinline__ uint32_t h2u(__half2 h) {
    return pack_halves(__low2half(h), __high2half(h));
}

__device__ __forceinline__ void ldsm_x4(uint32_t r[4], const __half* p) {
    uint32_t a = (uint32_t)__cvta_generic_to_shared(p);
    asm volatile("ldmatrix.sync.aligned.m8n8.x4.shared.b16 {%0,%1,%2,%3}, [%4];"
                 : "=r"(r[0]), "=r"(r[1]), "=r"(r[2]), "=r"(r[3]) : "r"(a));
}

__device__ __forceinline__ void ldsm_x4_t(uint32_t r[4], const __half* p) {
    uint32_t a = (uint32_t)__cvta_generic_to_shared(p);
    asm volatile("ldmatrix.sync.aligned.m8n8.x4.trans.shared.b16 {%0,%1,%2,%3}, [%4];"
                 : "=r"(r[0]), "=r"(r[1]), "=r"(r[2]), "=r"(r[3]) : "r"(a));
}

__device__ __forceinline__ void mma16816(float* c, const uint32_t a[4],
                                         uint32_t b0, uint32_t b1) {
    asm volatile(
        "mma.sync.aligned.m16n8k16.row.col.f32.f16.f16.f32 "
        "{%0,%1,%2,%3}, {%4,%5,%6,%7}, {%8,%9}, {%0,%1,%2,%3};\n"
        : "+f"(c[0]), "+f"(c[1]), "+f"(c[2]), "+f"(c[3])
        : "r"(a[0]), "r"(a[1]), "r"(a[2]), "r"(a[3]), "r"(b0), "r"(b1));
}

__global__ __launch_bounds__(256, 3)
void attn_kernel(const float* __restrict__ gq_base,
                 const float* __restrict__ gk_base,
                 const float* __restrict__ gv_base,
                 float* __restrict__ gout_base) {
    extern __shared__ __half smem[];
    __half* Ks = smem;                    // [SEQ][KSTR]
    __half* Vs = Ks + SEQ * KSTR;         // [SEQ][KSTR]
    __half* Qs = Vs + SEQ * KSTR;         // [QT][KSTR]

    const int bh  = blockIdx.y;
    const int q0  = blockIdx.x * QT;
    const int tid = threadIdx.x;

    const float* gq = gq_base + (size_t)bh * SEQ * D + (size_t)q0 * D;
    const float* gk = gk_base + (size_t)bh * SEQ * D;
    const float* gv = gv_base + (size_t)bh * SEQ * D;

    // ---- Load K, V (256x32 f32) and Q (128x32 f32), convert to fp16 smem ----
    #pragma unroll
    for (int c = tid; c < SEQ * 8; c += 256) {
        int r = c >> 3, s = c & 7;
        float4 kv = ((const float4*)(gk + r * D))[s];
        float4 vv = ((const float4*)(gv + r * D))[s];
        uint2 kp = make_uint2(h2u(__floats2half2_rn(kv.x, kv.y)),
                              h2u(__floats2half2_rn(kv.z, kv.w)));
        uint2 vp = make_uint2(h2u(__floats2half2_rn(vv.x, vv.y)),
                              h2u(__floats2half2_rn(vv.z, vv.w)));
        *(uint2*)(Ks + r * KSTR + s * 4) = kp;
        *(uint2*)(Vs + r * KSTR + s * 4) = vp;
    }
    #pragma unroll
    for (int c = tid; c < QT * 8; c += 256) {
        int r = c >> 3, s = c & 7;
        float4 qv = ((const float4*)(gq + r * D))[s];
        uint2 qp = make_uint2(h2u(__floats2half2_rn(qv.x, qv.y)),
                              h2u(__floats2half2_rn(qv.z, qv.w)));
        *(uint2*)(Qs + r * KSTR + s * 4) = qp;
    }
    __syncthreads();

    const int warp = tid >> 5;
    const int lane = tid & 31;
    const int gid  = lane >> 2;   // 0..7
    const int tig  = lane & 3;    // 0..3
    const int rowA = warp * 16;   // this warp owns rows rowA..rowA+15 for ALL keys

    // ---- Q A-fragments via ldmatrix.x4 ----
    uint32_t aQ[2][4];
    #pragma unroll
    for (int kc = 0; kc < 2; kc++)
        ldsm_x4(aQ[kc], Qs + (rowA + (lane & 15)) * KSTR + kc * 16 + (lane >> 4) * 8);

    const float inv_scale = 1.0f / 5.656854249492381f;

    // ---- Online softmax over 4 chunks of 64 keys ----
    float o[4][4];
    #pragma unroll
    for (int nt = 0; nt < 4; nt++) o[nt][0] = o[nt][1] = o[nt][2] = o[nt][3] = 0.f;
    float m_lo = -1e30f, m_hi = -1e30f, sum_lo = 0.f, sum_hi = 0.f;

    #pragma unroll
    for (int ch = 0; ch < 4; ch++) {
        const int cb = ch * 64;

        // QK^T for 16 rows x 64 keys (fp32 accum)
        float s[8][4];
        #pragma unroll
        for (int g = 0; g < 8; g++) s[g][0] = s[g][1] = s[g][2] = s[g][3] = 0.f;
        #pragma unroll
        for (int g = 0; g < 8; g++) {
            uint32_t kb[4];
            ldsm_x4(kb, Ks + (cb + g * 8 + (lane & 7)) * KSTR + (lane >> 3) * 8);
            mma16816(s[g], aQ[0], kb[0], kb[1]);
            mma16816(s[g], aQ[1], kb[2], kb[3]);
        }

        // scale + round to fp16 (packed RN, identical numerics)
        #pragma unroll
        for (int g = 0; g < 8; g++) {
            float2 f01 = __half22float2(__floats2half2_rn(s[g][0] * inv_scale,
                                                          s[g][1] * inv_scale));
            float2 f23 = __half22float2(__floats2half2_rn(s[g][2] * inv_scale,
                                                          s[g][3] * inv_scale));
            s[g][0] = f01.x; s[g][1] = f01.y; s[g][2] = f23.x; s[g][3] = f23.y;
        }

        // chunk max (per row half), reduced across the quad
        float cm_lo = -1e30f, cm_hi = -1e30f;
        #pragma unroll
        for (int g = 0; g < 8; g++) {
            cm_lo = fmaxf(cm_lo, fmaxf(s[g][0], s[g][1]));
            cm_hi = fmaxf(cm_hi, fmaxf(s[g][2], s[g][3]));
        }
        cm_lo = fmaxf(cm_lo, __shfl_xor_sync(0xffffffffu, cm_lo, 1));
        cm_lo = fmaxf(cm_lo, __shfl_xor_sync(0xffffffffu, cm_lo, 2));
        cm_hi = fmaxf(cm_hi, __shfl_xor_sync(0xffffffffu, cm_hi, 1));
        cm_hi = fmaxf(cm_hi, __shfl_xor_sync(0xffffffffu, cm_hi, 2));

        // online merge: rescale running O and sum
        float nm_lo = fmaxf(m_lo, cm_lo), nm_hi = fmaxf(m_hi, cm_hi);
        float al_lo = __expf(m_lo - nm_lo), al_hi = __expf(m_hi - nm_hi);
        #pragma unroll
        for (int nt = 0; nt < 4; nt++) {
            o[nt][0] *= al_lo; o[nt][1] *= al_lo;
            o[nt][2] *= al_hi; o[nt][3] *= al_hi;
        }

        float cs_lo = 0.f, cs_hi = 0.f;
        #pragma unroll
        for (int g = 0; g < 8; g++) {
            s[g][0] = __expf(s[g][0] - nm_lo);  cs_lo += s[g][0];
            s[g][1] = __expf(s[g][1] - nm_lo);  cs_lo += s[g][1];
            s[g][2] = __expf(s[g][2] - nm_hi);  cs_hi += s[g][2];
            s[g][3] = __expf(s[g][3] - nm_hi);  cs_hi += s[g][3];
        }
        cs_lo += __shfl_xor_sync(0xffffffffu, cs_lo, 1);
        cs_lo += __shfl_xor_sync(0xffffffffu, cs_lo, 2);
        cs_hi += __shfl_xor_sync(0xffffffffu, cs_hi, 1);
        cs_hi += __shfl_xor_sync(0xffffffffu, cs_hi, 2);

        sum_lo = sum_lo * al_lo + cs_lo;
        sum_hi = sum_hi * al_hi + cs_hi;
        m_lo = nm_lo; m_hi = nm_hi;

        // PV over this chunk: P = fp16(exp(s - m)), normalization deferred
        #pragma unroll
        for (int kc = 0; kc < 4; kc++) {
            uint32_t a[4];
            a[0] = h2u(__floats2half2_rn(s[2*kc][0],   s[2*kc][1]));
            a[1] = h2u(__floats2half2_rn(s[2*kc][2],   s[2*kc][3]));
            a[2] = h2u(__floats2half2_rn(s[2*kc+1][0], s[2*kc+1][1]));
            a[3] = h2u(__floats2half2_rn(s[2*kc+1][2], s[2*kc+1][3]));

            const __half* vbase = Vs + (cb + kc * 16 + (lane & 15)) * KSTR
                                     + ((lane >> 4) & 1) * 8;
            uint32_t vb[4];   // d cols 0-15
            ldsm_x4_t(vb, vbase);
            mma16816(o[0], a, vb[0], vb[1]);
            mma16816(o[1], a, vb[2], vb[3]);
            uint32_t vb2[4];  // d cols 16-31
            ldsm_x4_t(vb2, vbase + 16);
            mma16816(o[2], a, vb2[0], vb2[1]);
            mma16816(o[3], a, vb2[2], vb2[3]);
        }
    }

    // ---- Final normalization + emit (no cross-warp combine needed) ----
    const float sc_lo = 1.f / sum_lo;
    const float sc_hi = 1.f / sum_hi;
    float* go = gout_base + (size_t)bh * SEQ * D + (size_t)(q0 + rowA) * D;
    #pragma unroll
    for (int nt = 0; nt < 4; nt++) {
        int c = nt * 8 + tig * 2;
        float2 lo = __half22float2(__floats2half2_rn(o[nt][0] * sc_lo, o[nt][1] * sc_lo));
        float2 hi = __half22float2(__floats2half2_rn(o[nt][2] * sc_hi, o[nt][3] * sc_hi));
        *(float2*)(go + (gid)     * D + c) = lo;
        *(float2*)(go + (gid + 8) * D + c) = hi;
    }
}

extern "C" void kernel_launch(void* const* d_in, const int* in_sizes, int n_in,
                              void* d_out, int out_size) {
    const float* q = (const float*)d_in[0];
    const float* k = (const float*)d_in[1];
    const float* v = (const float*)d_in[2];
    float* out = (float*)d_out;

    cudaFuncSetAttribute(attn_kernel, cudaFuncAttributeMaxDynamicSharedMemorySize, SMEM_BYTES);

    dim3 grid(SEQ / QT, BATCH * HEADS);
    attn_kernel<<<grid, 256, SMEM_BYTES>>>(q, k, v, out);
}

// round 11
// speedup vs baseline: 1.4031x; 1.0137x over previous
#include <cuda_runtime.h>
#include <cuda_fp16.h>
#include <cstdint>

#define BATCH 16
#define HEADS 16
#define SEQ   256
#define D     32
#define QT    128           // query rows per CTA (one warp = 16 rows x all 256 keys)
#define KSTR  40            // halves per K/V/Q smem row (80B pitch, LDSM conflict-free)

// halves: Ks 256*40 + Vs 256*40 + Qs 128*40 = 25600 -> 51200 B
#define SMEM_BYTES 51200

__device__ __forceinline__ uint32_t pack_halves(__half lo, __half hi) {
    return (uint32_t)__half_as_ushort(lo) | ((uint32_t)__half_as_ushort(hi) << 16);
}

__device__ __forceinline__ uint32_t h2u(__half2 h) {
    return pack_halves(__low2half(h), __high2half(h));
}

__device__ __forceinline__ void ldsm_x4(uint32_t r[4], const __half* p) {
    uint32_t a = (uint32_t)__cvta_generic_to_shared(p);
    asm volatile("ldmatrix.sync.aligned.m8n8.x4.shared.b16 {%0,%1,%2,%3}, [%4];"
                 : "=r"(r[0]), "=r"(r[1]), "=r"(r[2]), "=r"(r[3]) : "r"(a));
}

__device__ __forceinline__ void ldsm_x4_t(uint32_t r[4], const __half* p) {
    uint32_t a = (uint32_t)__cvta_generic_to_shared(p);
    asm volatile("ldmatrix.sync.aligned.m8n8.x4.trans.shared.b16 {%0,%1,%2,%3}, [%4];"
                 : "=r"(r[0]), "=r"(r[1]), "=r"(r[2]), "=r"(r[3]) : "r"(a));
}

__device__ __forceinline__ void mma16816(float* c, const uint32_t a[4],
                                         uint32_t b0, uint32_t b1) {
    asm volatile(
        "mma.sync.aligned.m16n8k16.row.col.f32.f16.f16.f32 "
        "{%0,%1,%2,%3}, {%4,%5,%6,%7}, {%8,%9}, {%0,%1,%2,%3};\n"
        : "+f"(c[0]), "+f"(c[1]), "+f"(c[2]), "+f"(c[3])
        : "r"(a[0]), "r"(a[1]), "r"(a[2]), "r"(a[3]), "r"(b0), "r"(b1));
}

__global__ __launch_bounds__(256, 4)
void attn_kernel(const float* __restrict__ gq_base,
                 const float* __restrict__ gk_base,
                 const float* __restrict__ gv_base,
                 float* __restrict__ gout_base) {
    extern __shared__ __half smem[];
    __half* Ks = smem;                    // [SEQ][KSTR]
    __half* Vs = Ks + SEQ * KSTR;         // [SEQ][KSTR]
    __half* Qs = Vs + SEQ * KSTR;         // [QT][KSTR]

    const int bh  = blockIdx.y;
    const int q0  = blockIdx.x * QT;
    const int tid = threadIdx.x;

    const float* gq = gq_base + (size_t)bh * SEQ * D + (size_t)q0 * D;
    const float* gk = gk_base + (size_t)bh * SEQ * D;
    const float* gv = gv_base + (size_t)bh * SEQ * D;

    // ---- Load K, V (256x32 f32) and Q (128x32 f32), convert to fp16 smem ----
    #pragma unroll
    for (int c = tid; c < SEQ * 8; c += 256) {
        int r = c >> 3, s = c & 7;
        float4 kv = ((const float4*)(gk + r * D))[s];
        float4 vv = ((const float4*)(gv + r * D))[s];
        uint2 kp = make_uint2(h2u(__floats2half2_rn(kv.x, kv.y)),
                              h2u(__floats2half2_rn(kv.z, kv.w)));
        uint2 vp = make_uint2(h2u(__floats2half2_rn(vv.x, vv.y)),
                              h2u(__floats2half2_rn(vv.z, vv.w)));
        *(uint2*)(Ks + r * KSTR + s * 4) = kp;
        *(uint2*)(Vs + r * KSTR + s * 4) = vp;
    }
    #pragma unroll
    for (int c = tid; c < QT * 8; c += 256) {
        int r = c >> 3, s = c & 7;
        float4 qv = ((const float4*)(gq + r * D))[s];
        uint2 qp = make_uint2(h2u(__floats2half2_rn(qv.x, qv.y)),
                              h2u(__floats2half2_rn(qv.z, qv.w)));
        *(uint2*)(Qs + r * KSTR + s * 4) = qp;
    }
    __syncthreads();

    const int warp = tid >> 5;
    const int lane = tid & 31;
    const int gid  = lane >> 2;   // 0..7
    const int tig  = lane & 3;    // 0..3
    const int rowA = warp * 16;   // this warp owns rows rowA..rowA+15 for ALL keys

    // ---- Q A-fragments via ldmatrix.x4 ----
    uint32_t aQ[2][4];
    #pragma unroll
    for (int kc = 0; kc < 2; kc++)
        ldsm_x4(aQ[kc], Qs + (rowA + (lane & 15)) * KSTR + kc * 16 + (lane >> 4) * 8);

    const float inv_scale = 1.0f / 5.656854249492381f;

    // ---- Online softmax over 8 chunks of 32 keys ----
    float o[4][4];
    #pragma unroll
    for (int nt = 0; nt < 4; nt++) o[nt][0] = o[nt][1] = o[nt][2] = o[nt][3] = 0.f;
    float m_lo = -1e30f, m_hi = -1e30f, sum_lo = 0.f, sum_hi = 0.f;

    #pragma unroll
    for (int ch = 0; ch < 8; ch++) {
        const int cb = ch * 32;

        // QK^T for 16 rows x 32 keys (fp32 accum)
        float s[4][4];
        #pragma unroll
        for (int g = 0; g < 4; g++) s[g][0] = s[g][1] = s[g][2] = s[g][3] = 0.f;
        #pragma unroll
        for (int g = 0; g < 4; g++) {
            uint32_t kb[4];
            ldsm_x4(kb, Ks + (cb + g * 8 + (lane & 7)) * KSTR + (lane >> 3) * 8);
            mma16816(s[g], aQ[0], kb[0], kb[1]);
            mma16816(s[g], aQ[1], kb[2], kb[3]);
        }

        // scale + round to fp16 (packed RN, identical numerics)
        #pragma unroll
        for (int g = 0; g < 4; g++) {
            float2 f01 = __half22float2(__floats2half2_rn(s[g][0] * inv_scale,
                                                          s[g][1] * inv_scale));
            float2 f23 = __half22float2(__floats2half2_rn(s[g][2] * inv_scale,
                                                          s[g][3] * inv_scale));
            s[g][0] = f01.x; s[g][1] = f01.y; s[g][2] = f23.x; s[g][3] = f23.y;
        }

        // chunk max (per row half), reduced across the quad
        float cm_lo = -1e30f, cm_hi = -1e30f;
        #pragma unroll
        for (int g = 0; g < 4; g++) {
            cm_lo = fmaxf(cm_lo, fmaxf(s[g][0], s[g][1]));
            cm_hi = fmaxf(cm_hi, fmaxf(s[g][2], s[g][3]));
        }
        cm_lo = fmaxf(cm_lo, __shfl_xor_sync(0xffffffffu, cm_lo, 1));
        cm_lo = fmaxf(cm_lo, __shfl_xor_sync(0xffffffffu, cm_lo, 2));
        cm_hi = fmaxf(cm_hi, __shfl_xor_sync(0xffffffffu, cm_hi, 1));
        cm_hi = fmaxf(cm_hi, __shfl_xor_sync(0xffffffffu, cm_hi, 2));

        // online merge: rescale running O and sum
        float nm_lo = fmaxf(m_lo, cm_lo), nm_hi = fmaxf(m_hi, cm_hi);
        float al_lo = __expf(m_lo - nm_lo), al_hi = __expf(m_hi - nm_hi);
        #pragma unroll
        for (int nt = 0; nt < 4; nt++) {
            o[nt][0] *= al_lo; o[nt][1] *= al_lo;
            o[nt][2] *= al_hi; o[nt][3] *= al_hi;
        }

        float cs_lo = 0.f, cs_hi = 0.f;
        #pragma unroll
        for (int g = 0; g < 4; g++) {
            s[g][0] = __expf(s[g][0] - nm_lo);  cs_lo += s[g][0];
            s[g][1] = __expf(s[g][1] - nm_lo);  cs_lo += s[g][1];
            s[g][2] = __expf(s[g][2] - nm_hi);  cs_hi += s[g][2];
            s[g][3] = __expf(s[g][3] - nm_hi);  cs_hi += s[g][3];
        }
        cs_lo += __shfl_xor_sync(0xffffffffu, cs_lo, 1);
        cs_lo += __shfl_xor_sync(0xffffffffu, cs_lo, 2);
        cs_hi += __shfl_xor_sync(0xffffffffu, cs_hi, 1);
        cs_hi += __shfl_xor_sync(0xffffffffu, cs_hi, 2);

        sum_lo = sum_lo * al_lo + cs_lo;
        sum_hi = sum_hi * al_hi + cs_hi;
        m_lo = nm_lo; m_hi = nm_hi;

        // PV over this chunk: P = fp16(exp(s - m)), normalization deferred
        #pragma unroll
        for (int kc = 0; kc < 2; kc++) {
            uint32_t a[4];
            a[0] = h2u(__floats2half2_rn(s[2*kc][0],   s[2*kc][1]));
            a[1] = h2u(__floats2half2_rn(s[2*kc][2],   s[2*kc][3]));
            a[2] = h2u(__floats2half2_rn(s[2*kc+1][0], s[2*kc+1][1]));
            a[3] = h2u(__floats2half2_rn(s[2*kc+1][2], s[2*kc+1][3]));

            const __half* vbase = Vs + (cb + kc * 16 + (lane & 15)) * KSTR
                                     + ((lane >> 4) & 1) * 8;
            uint32_t vb[4];   // d cols 0-15
            ldsm_x4_t(vb, vbase);
            mma16816(o[0], a, vb[0], vb[1]);
            mma16816(o[1], a, vb[2], vb[3]);
            uint32_t vb2[4];  // d cols 16-31
            ldsm_x4_t(vb2, vbase + 16);
            mma16816(o[2], a, vb2[0], vb2[1]);
            mma16816(o[3], a, vb2[2], vb2[3]);
        }
    }

    // ---- Final normalization + emit (no cross-warp combine needed) ----
    const float sc_lo = 1.f / sum_lo;
    const float sc_hi = 1.f / sum_hi;
    float* go = gout_base + (size_t)bh * SEQ * D + (size_t)(q0 + rowA) * D;
    #pragma unroll
    for (int nt = 0; nt < 4; nt++) {
        int c = nt * 8 + tig * 2;
        float2 lo = __half22float2(__floats2half2_rn(o[nt][0] * sc_lo, o[nt][1] * sc_lo));
        float2 hi = __half22float2(__floats2half2_rn(o[nt][2] * sc_hi, o[nt][3] * sc_hi));
        *(float2*)(go + (gid)     * D + c) = lo;
        *(float2*)(go + (gid + 8) * D + c) = hi;
    }
}

extern "C" void kernel_launch(void* const* d_in, const int* in_sizes, int n_in,
                              void* d_out, int out_size) {
    const float* q = (const float*)d_in[0];
    const float* k = (const float*)d_in[1];
    const float* v = (const float*)d_in[2];
    float* out = (float*)d_out;

    cudaFuncSetAttribute(attn_kernel, cudaFuncAttributeMaxDynamicSharedMemorySize, SMEM_BYTES);

    dim3 grid(SEQ / QT, BATCH * HEADS);
    attn_kernel<<<grid, 256, SMEM_BYTES>>>(q, k, v, out);
}